// round 16
// baseline (speedup 1.0000x reference)
#include <cuda_runtime.h>
#include <cuda_fp16.h>
#include <cstdint>

#define B_   2
#define SQ_  2048
#define SK_  2048
#define D_   1024
#define H_   16
#define HD_  64
#define P_   257
#define R_   128
#define RAD_ 256

#define GST 36             // gemm smem row stride in uint32 units
#define AST 36             // attention smem row stride in uint32 units
#define ATILE (64 * AST)
#define QROWS 128
#define HS ((size_t)B_ * H_ * SQ_ * HD_)

// ---------------- scratch (device globals; no allocation allowed) -----------
__device__ __half g_xf[3][(size_t)B_ * SQ_ * D_];
__device__ __half g_wh[4][(size_t)D_ * D_];
__device__ __half g_heads[3 * HS];                 // qh | kh | vh
__device__ __half g_relT[(size_t)H_ * P_ * HD_];
__device__ float  g_qrel[(size_t)B_ * H_ * SQ_ * P_];
__device__ __half g_o[(size_t)B_ * SQ_ * D_];

// ---------------- helpers ----------------------------------------------------
__device__ __forceinline__ void mma_h(float* c, const uint32_t* a, const uint32_t* b) {
    asm volatile(
        "mma.sync.aligned.m16n8k16.row.col.f32.f16.f16.f32 "
        "{%0,%1,%2,%3}, {%4,%5,%6,%7}, {%8,%9}, {%0,%1,%2,%3};"
        : "+f"(c[0]), "+f"(c[1]), "+f"(c[2]), "+f"(c[3])
        : "r"(a[0]), "r"(a[1]), "r"(a[2]), "r"(a[3]), "r"(b[0]), "r"(b[1]));
}

__device__ __forceinline__ void ldsm4(uint32_t* r, uint32_t saddr) {
    asm volatile("ldmatrix.sync.aligned.m8n8.x4.shared.b16 {%0,%1,%2,%3}, [%4];"
                 : "=r"(r[0]), "=r"(r[1]), "=r"(r[2]), "=r"(r[3]) : "r"(saddr));
}

__device__ __forceinline__ void ldsm4t(uint32_t* r, uint32_t saddr) {
    asm volatile("ldmatrix.sync.aligned.m8n8.x4.trans.shared.b16 {%0,%1,%2,%3}, [%4];"
                 : "=r"(r[0]), "=r"(r[1]), "=r"(r[2]), "=r"(r[3]) : "r"(saddr));
}

__device__ __forceinline__ void cp16(void* dst_s, const void* src_g, int sz) {
    uint32_t dst = (uint32_t)__cvta_generic_to_shared(dst_s);
    asm volatile("cp.async.cg.shared.global [%0], [%1], 16, %2;\n"
                 :: "r"(dst), "l"(src_g), "r"(sz));
}

__device__ __forceinline__ uint32_t s2u(const void* p) {
    return (uint32_t)__cvta_generic_to_shared(p);
}

__device__ __forceinline__ uint32_t packh2(float x, float y) {
    __half2 h = __floats2half2_rn(x, y);
    return *(uint32_t*)&h;
}

// ---------------- prologue conversions ---------------------------------------
__global__ void cvt_qkv(const float* __restrict__ Q, const float* __restrict__ K,
                        const float* __restrict__ V, __half* __restrict__ qf,
                        __half* __restrict__ kf, __half* __restrict__ vf, int n4)
{
    int i = blockIdx.x * blockDim.x + threadIdx.x;
    if (i >= n4) return;
    float4 a = ((const float4*)Q)[i];
    ((uint2*)qf)[i] = make_uint2(packh2(a.x, a.y), packh2(a.z, a.w));
    float4 b = ((const float4*)K)[i];
    ((uint2*)kf)[i] = make_uint2(packh2(b.x, b.y), packh2(b.z, b.w));
    float4 c = ((const float4*)V)[i];
    ((uint2*)vf)[i] = make_uint2(packh2(c.x, c.y), packh2(c.z, c.w));
}

__global__ void cvt_w(const float* __restrict__ w0, const float* __restrict__ w1,
                      const float* __restrict__ w2, const float* __restrict__ w3,
                      __half* __restrict__ dst, int n4)
{
    int i = blockIdx.x * blockDim.x + threadIdx.x;
    if (i >= n4) return;
    const float* srcs[4] = {w0, w1, w2, w3};
#pragma unroll
    for (int m = 0; m < 4; m++) {
        float4 a = ((const float4*)srcs[m])[i];
        ((uint2*)(dst + (size_t)m * D_ * D_))[i] =
            make_uint2(packh2(a.x, a.y), packh2(a.z, a.w));
    }
}

__global__ void transpose_E(const float* __restrict__ E, __half* __restrict__ relT)
{
    int idx = blockIdx.x * blockDim.x + threadIdx.x;
    if (idx >= H_ * P_ * HD_) return;
    int h = idx / (P_ * HD_);
    int rem = idx % (P_ * HD_);
    int p = rem / HD_;
    int d = rem % HD_;
    relT[idx] = __float2half(E[(long long)p * D_ + d * H_ + h]);
}

// ---------------- fp16 tensor-core NT GEMM (3-stage, 1 barrier/ktile) -------
// MODE 0: C fp32 row-major, row stride ldC (scalar stores — ldC may be odd).
// MODE 1: head-split epilogue, C fp16 (paired 4B stores).
// MODE 2: C fp32 row-major, ldC EVEN (paired float2 stores).
template <int MODE>
__global__ __launch_bounds__(256, 2) void gemm_h(
    const __half* __restrict__ A, const __half* __restrict__ Bm,
    void* __restrict__ Cv, int M, int N, int K, int ldC,
    long long sA, long long sB, long long sC, int bmodB)
{
    extern __shared__ uint32_t smh[];   // 3 stages * 2 * 128 * GST
    const int z = blockIdx.z;
    A  += (long long)z * sA;
    Bm += (long long)(z % bmodB) * sB;
    float*  Cf = (float*)Cv  + (long long)z * sC;
    __half* Ch = (__half*)Cv + (long long)z * sC;

    const int bm = blockIdx.y * 128, bn = blockIdx.x * 128;
    const int tid = threadIdx.x;
    const int wid = tid >> 5, lane = tid & 31;
    const int wm = (wid & 3) * 32, wn = (wid >> 2) * 64;
    const int q = lane >> 2, t = lane & 3;

    const uint32_t sbase = s2u(smh);
    const uint32_t STAGEB = 2 * 128 * GST * 4;
    const uint32_t a_byte = (uint32_t)(wm + (lane & 15)) * (GST * 4) + ((lane >> 4) << 4);
    const uint32_t b_byte = (uint32_t)(wn + (lane & 7) + ((lane & 16) ? 8 : 0)) * (GST * 4)
                            + ((lane & 8) ? 16 : 0);

    float acc[2][8][4];
#pragma unroll
    for (int mi = 0; mi < 2; mi++)
#pragma unroll
        for (int ni = 0; ni < 8; ni++)
#pragma unroll
            for (int e = 0; e < 4; e++) acc[mi][ni][e] = 0.f;

    const int ktiles = K >> 6;

#define ISSUE(KT, STAGE)                                                      \
    {                                                                         \
        uint32_t* As = smh + (STAGE) * (2 * 128 * GST);                       \
        uint32_t* Bs = As + 128 * GST;                                        \
        int k0 = (KT) * 64;                                                   \
        _Pragma("unroll")                                                     \
        for (int rep = 0; rep < 4; rep++) {                                   \
            int idx = rep * 256 + tid;                                        \
            int row = idx >> 3, ch = idx & 7;                                 \
            cp16(As + row * GST + ch * 4,                                     \
                 A + (long long)(bm + row) * K + k0 + ch * 8, 16);            \
            int gb = bn + row;                                                \
            int gbc = gb < N ? gb : (N - 1);                                  \
            cp16(Bs + row * GST + ch * 4,                                     \
                 Bm + (long long)gbc * K + k0 + ch * 8, (gb < N) ? 16 : 0);   \
        }                                                                     \
        asm volatile("cp.async.commit_group;\n");                             \
    }

    ISSUE(0, 0);
    if (ktiles > 1) ISSUE(1, 1);

    for (int kt = 0; kt < ktiles; kt++) {
        if (kt + 1 < ktiles) {
            asm volatile("cp.async.wait_group 1;\n");
        } else {
            asm volatile("cp.async.wait_group 0;\n");
        }
        __syncthreads();
        if (kt + 2 < ktiles) ISSUE(kt + 2, (kt + 2) % 3);

        const uint32_t As_s = sbase + (kt % 3) * STAGEB;
        const uint32_t Bs_s = As_s + 128 * GST * 4;
#pragma unroll
        for (int ks = 0; ks < 4; ks++) {
            const uint32_t kbB = ks * 32;
            uint32_t af[2][4];
            ldsm4(af[0], As_s + a_byte + kbB);
            ldsm4(af[1], As_s + a_byte + 16 * GST * 4 + kbB);
            uint32_t bf[8][2];
#pragma unroll
            for (int nj = 0; nj < 4; nj++) {
                uint32_t r[4];
                ldsm4(r, Bs_s + b_byte + nj * 16 * GST * 4 + kbB);
                bf[2 * nj][0] = r[0]; bf[2 * nj][1] = r[1];
                bf[2 * nj + 1][0] = r[2]; bf[2 * nj + 1][1] = r[3];
            }
#pragma unroll
            for (int mi = 0; mi < 2; mi++)
#pragma unroll
                for (int ni = 0; ni < 8; ni++)
                    mma_h(acc[mi][ni], af[mi], bf[ni]);
        }
    }
#undef ISSUE

    // ---- epilogue ----
#pragma unroll
    for (int mi = 0; mi < 2; mi++)
#pragma unroll
        for (int ni = 0; ni < 8; ni++) {
            int gc0 = bn + wn + ni * 8 + t * 2;
#pragma unroll
            for (int half = 0; half < 2; half++) {        // (e0,e1) then (e2,e3)
                int gr = bm + wm + mi * 16 + q + half * 8;
                float v0 = acc[mi][ni][half * 2 + 0];
                float v1 = acc[mi][ni][half * 2 + 1];
                if (MODE == 0) {
                    if (gc0 < N)     Cf[(long long)gr * ldC + gc0]     = v0;
                    if (gc0 + 1 < N) Cf[(long long)gr * ldC + gc0 + 1] = v1;
                } else if (MODE == 2) {
                    *(float2*)(Cf + (long long)gr * ldC + gc0) = make_float2(v0, v1);
                } else {
                    int b = gr >> 11, s = gr & 2047;
                    int h = gc0 >> 6, hd = gc0 & 63;
                    *(uint32_t*)(Ch + (((long long)b * H_ + h) * SQ_ + s) * HD_ + hd) =
                        packh2(v0, v1);
                }
            }
        }
}

// ---------------- banded flash attention (static softmax + warp tile skip) --
__global__ __launch_bounds__(256, 2) void attn_mma(
    const __half* __restrict__ qh, const __half* __restrict__ kh,
    const __half* __restrict__ vh, const float* __restrict__ qrel,
    __half* __restrict__ O)
{
    extern __shared__ uint32_t sma[];
    uint32_t* Qs  = sma;
    uint32_t* Ks0 = Qs + QROWS * AST;
    uint32_t* Vs0 = Ks0 + 2 * ATILE;

    const int i0 = blockIdx.x * QROWS;
    const int h = blockIdx.y, b = blockIdx.z;
    const long long hb = (long long)(b * H_ + h);
    const uint32_t* qb = (const uint32_t*)(qh + hb * SQ_ * HD_);
    const uint32_t* kb = (const uint32_t*)(kh + hb * SK_ * HD_);
    const uint32_t* vb = (const uint32_t*)(vh + hb * SK_ * HD_);
    const float* qr = qrel + hb * SQ_ * P_;

    const int tid = threadIdx.x;
    const int wid = tid >> 5, lane = tid & 31;
    const int q = lane >> 2, t = lane & 3;
    const int wm = wid * 16;
    const int r0 = wm + q, r1 = r0 + 8;
    const int I0w = i0 + wm;               // first row owned by this warp

    const uint32_t sbase = s2u(sma);
    const uint32_t Qs_s = sbase;
    const uint32_t Kbase = sbase + QROWS * AST * 4;
    const uint32_t Vbase = Kbase + 2 * ATILE * 4;

    const uint32_t a_byte = (uint32_t)(wm + (lane & 15)) * (AST * 4) + ((lane >> 4) << 4);
    const uint32_t k_byte = (uint32_t)((lane & 7) + ((lane & 16) ? 8 : 0)) * (AST * 4)
                            + ((lane & 8) ? 16 : 0);
    const uint32_t v_byte = (uint32_t)((lane & 7) + ((lane & 8) ? 8 : 0)) * (AST * 4)
                            + ((lane & 16) ? 16 : 0);

#define AISSUE(J0, S)                                                         \
    {                                                                         \
        uint32_t* Kd = Ks0 + (S) * ATILE;                                     \
        uint32_t* Vd = Vs0 + (S) * ATILE;                                     \
        _Pragma("unroll")                                                     \
        for (int l = tid; l < 512; l += 256) {                                \
            int r = l >> 3, ch = l & 7;                                       \
            cp16(Kd + r * AST + ch * 4,                                       \
                 kb + (long long)((J0) + r) * 32 + ch * 4, 16);               \
            cp16(Vd + r * AST + ch * 4,                                       \
                 vb + (long long)((J0) + r) * 32 + ch * 4, 16);               \
        }                                                                     \
        asm volatile("cp.async.commit_group;\n");                             \
    }

    int lo = i0 - RAD_;           if (lo < 0) lo = 0;
    int hi = i0 + QROWS + RAD_;   if (hi > SK_) hi = SK_;

#pragma unroll
    for (int l = tid; l < 1024; l += 256) {
        int r = l >> 3, ch = l & 7;
        cp16(Qs + r * AST + ch * 4, qb + (long long)(i0 + r) * 32 + ch * 4, 16);
    }
    AISSUE(lo, 0);

    float l_part[2] = {0.f, 0.f};      // per-thread partial row sums
    float oacc[8][4];
#pragma unroll
    for (int ni = 0; ni < 8; ni++)
#pragma unroll
        for (int e = 0; e < 4; e++) oacc[ni][e] = 0.f;

    int stage = 0;
    for (int j0 = lo; j0 < hi; j0 += 64) {
        asm volatile("cp.async.wait_group 0;\n");
        __syncthreads();
        if (j0 + 64 < hi) AISSUE(j0 + 64, stage ^ 1);

        // warp-uniform skip: this key tile entirely outside this warp's band
        // (all rows [I0w, I0w+15]: every p would be exactly 0)
        bool live = (j0 <= I0w + 15 + RAD_) && (j0 + 63 >= I0w - RAD_);
        if (live) {
            const uint32_t Ks_s = Kbase + stage * ATILE * 4;
            const uint32_t Vs_s = Vbase + stage * ATILE * 4;

            // ---- S = Q K^T : 16 rows x 64 keys per warp ----
            float sacc[8][4];
#pragma unroll
            for (int ni = 0; ni < 8; ni++)
#pragma unroll
                for (int e = 0; e < 4; e++) sacc[ni][e] = 0.f;
#pragma unroll
            for (int ks = 0; ks < 4; ks++) {
                const uint32_t kbB = ks * 32;
                uint32_t af[4];
                ldsm4(af, Qs_s + a_byte + kbB);
#pragma unroll
                for (int nj = 0; nj < 4; nj++) {
                    uint32_t r[4];
                    ldsm4(r, Ks_s + k_byte + nj * 16 * AST * 4 + kbB);
                    uint32_t bf0[2] = {r[0], r[1]};
                    uint32_t bf1[2] = {r[2], r[3]};
                    mma_h(sacc[2 * nj], af, bf0);
                    mma_h(sacc[2 * nj + 1], af, bf1);
                }
            }

            // ---- rel gather + mask + scale + exp (no running max) ----
#pragma unroll
            for (int ni = 0; ni < 8; ni++)
#pragma unroll
                for (int e = 0; e < 4; e++) {
                    int ri = e >> 1;
                    int rl = ri ? r1 : r0;
                    int c = ni * 8 + t * 2 + (e & 1);
                    int delta = (j0 + c) - (i0 + rl);
                    float p = 0.f;
                    if (delta >= -RAD_ && delta <= RAD_) {
                        int pid = min(max(delta, -R_), R_) + R_;
                        float s = (sacc[ni][e] +
                                   __ldg(qr + (long long)(i0 + rl) * P_ + pid)) * 0.125f;
                        p = __expf(s);
                    }
                    sacc[ni][e] = p;
                    l_part[ri] += p;
                }

            // ---- O += P V : QK C-frags pass directly into PV A-frags ----
#pragma unroll
            for (int ks = 0; ks < 4; ks++) {
                uint32_t af[4];
                af[0] = packh2(sacc[2 * ks][0], sacc[2 * ks][1]);
                af[1] = packh2(sacc[2 * ks][2], sacc[2 * ks][3]);
                af[2] = packh2(sacc[2 * ks + 1][0], sacc[2 * ks + 1][1]);
                af[3] = packh2(sacc[2 * ks + 1][2], sacc[2 * ks + 1][3]);
#pragma unroll
                for (int nj = 0; nj < 4; nj++) {
                    uint32_t r[4];
                    ldsm4t(r, Vs_s + v_byte + ks * 16 * AST * 4 + nj * 32);
                    uint32_t bf0[2] = {r[0], r[1]};
                    uint32_t bf1[2] = {r[2], r[3]};
                    mma_h(oacc[2 * nj], af, bf0);
                    mma_h(oacc[2 * nj + 1], af, bf1);
                }
            }
        }
        stage ^= 1;
    }
#undef AISSUE

    // ---- one final row-sum reduction (quad shfl) + normalize + store ----
    float inv[2];
#pragma unroll
    for (int i = 0; i < 2; i++) {
        float s = l_part[i];
        s += __shfl_xor_sync(0xffffffffu, s, 1);
        s += __shfl_xor_sync(0xffffffffu, s, 2);
        inv[i] = 1.0f / s;
    }
#pragma unroll
    for (int ni = 0; ni < 8; ni++)
#pragma unroll
        for (int e = 0; e < 4; e++) {
            int ri = e >> 1;
            int rl = ri ? r1 : r0;
            int c = ni * 8 + t * 2 + (e & 1);
            O[((long long)b * SQ_ + i0 + rl) * D_ + c * H_ + h] =
                __float2half(oacc[ni][e] * inv[ri]);
        }
}

// ---------------- launch -----------------------------------------------------
extern "C" void kernel_launch(void* const* d_in, const int* in_sizes, int n_in,
                              void* d_out, int out_size)
{
    const float* Q  = (const float*)d_in[0];
    const float* K  = (const float*)d_in[1];
    const float* V  = (const float*)d_in[2];
    const float* Wq = (const float*)d_in[3];
    const float* Wk = (const float*)d_in[4];
    const float* Wv = (const float*)d_in[5];
    const float* Wo = (const float*)d_in[6];
    const float* E  = (const float*)d_in[7];
    float* out = (float*)d_out;

    __half *xf, *wh, *heads, *relT, *o;
    float *qrel;
    cudaGetSymbolAddress((void**)&xf,    g_xf);
    cudaGetSymbolAddress((void**)&wh,    g_wh);
    cudaGetSymbolAddress((void**)&heads, g_heads);
    cudaGetSymbolAddress((void**)&relT,  g_relT);
    cudaGetSymbolAddress((void**)&qrel,  g_qrel);
    cudaGetSymbolAddress((void**)&o,     g_o);

    __half* qf = xf + 0 * (size_t)B_ * SQ_ * D_;
    __half* kf = xf + 1 * (size_t)B_ * SQ_ * D_;
    __half* vf = xf + 2 * (size_t)B_ * SQ_ * D_;
    __half* qh = heads;
    __half* kh = heads + HS;
    __half* vh = heads + 2 * HS;

    const int gemm_smem = 3 * 2 * 128 * GST * (int)sizeof(uint32_t);   // 110592
    cudaFuncSetAttribute((const void*)gemm_h<0>, cudaFuncAttributeMaxDynamicSharedMemorySize, gemm_smem);
    cudaFuncSetAttribute((const void*)gemm_h<1>, cudaFuncAttributeMaxDynamicSharedMemorySize, gemm_smem);
    cudaFuncSetAttribute((const void*)gemm_h<2>, cudaFuncAttributeMaxDynamicSharedMemorySize, gemm_smem);

    dim3 blk(256);

    // prologue conversions
    int nx4 = B_ * SQ_ * D_ / 4;
    cvt_qkv<<<(nx4 + 255) / 256, 256>>>(Q, K, V, qf, kf, vf, nx4);
    int nW4 = D_ * D_ / 4;
    cvt_w<<<(nW4 + 255) / 256, 256>>>(Wq, Wk, Wv, Wo, wh, nW4);
    int nE = H_ * P_ * HD_;
    transpose_E<<<(nE + 255) / 256, 256>>>(E, relT);

    // fused Q/K/V projections (z selects input/weight/output)
    dim3 gproj(1024 / 128, 4096 / 128, 3);
    gemm_h<1><<<gproj, blk, gemm_smem>>>(qf, wh, heads, 4096, 1024, 1024, 0,
                                         (long long)B_ * SQ_ * D_, (long long)D_ * D_,
                                         (long long)HS, 3);

    // Q_rel (N=257, odd ldC -> scalar store path)
    dim3 gqr((P_ + 127) / 128, SQ_ / 128, B_ * H_);
    gemm_h<0><<<gqr, blk, gemm_smem>>>(qh, relT, qrel, SQ_, P_, HD_, P_,
                                       (long long)SQ_ * HD_, (long long)P_ * HD_,
                                       (long long)SQ_ * P_, H_);

    // banded attention (static softmax + warp-level tile skip)
    int asmem = (QROWS * AST + 4 * ATILE) * (int)sizeof(uint32_t);   // 55296
    cudaFuncSetAttribute(attn_mma, cudaFuncAttributeMaxDynamicSharedMemorySize, asmem);
    dim3 gattn(SQ_ / QROWS, H_, B_);
    attn_mma<<<gattn, blk, asmem>>>(qh, kh, vh, qrel, o);

    // output projection -> fp32 out (even ldC -> paired float2 stores)
    dim3 gout(1024 / 128, 4096 / 128, 1);
    gemm_h<2><<<gout, blk, gemm_smem>>>(o, wh + 3 * (size_t)D_ * D_, out,
                                        4096, 1024, 1024, 1024, 0, 0, 0, 1);

    (void)in_sizes; (void)n_in; (void)out_size;
}

// round 17
// speedup vs baseline: 1.0386x; 1.0386x over previous
#include <cuda_runtime.h>
#include <cuda_fp16.h>
#include <cstdint>

#define B_   2
#define SQ_  2048
#define SK_  2048
#define D_   1024
#define H_   16
#define HD_  64
#define P_   257
#define R_   128
#define RAD_ 256

#define GST 36             // gemm smem row stride in uint32 units
#define AST 36             // attention smem row stride in uint32 units
#define ATILE (64 * AST)
#define QROWS 128
#define HS ((size_t)B_ * H_ * SQ_ * HD_)

// fused prologue block partition
#define NX4   (B_ * SQ_ * D_ / 4)          // 1048576 qkv float4s
#define NW4   (D_ * D_ / 4)                // 262144 weight float4s
#define NE    (H_ * P_ * HD_)              // 263168 E elements
#define BLK_QKV ((NX4 + 255) / 256)        // 4096
#define BLK_W   ((NW4 + 255) / 256)        // 1024
#define BLK_E   ((NE + 255) / 256)         // 1028

// ---------------- scratch (device globals; no allocation allowed) -----------
__device__ __half g_xf[3][(size_t)B_ * SQ_ * D_];
__device__ __half g_wh[4][(size_t)D_ * D_];
__device__ __half g_heads[3 * HS];                 // qh | kh | vh
__device__ __half g_relT[(size_t)H_ * P_ * HD_];
__device__ float  g_qrel[(size_t)B_ * H_ * SQ_ * P_];
__device__ __half g_o[(size_t)B_ * SQ_ * D_];

// ---------------- helpers ----------------------------------------------------
__device__ __forceinline__ void mma_h(float* c, const uint32_t* a, const uint32_t* b) {
    asm volatile(
        "mma.sync.aligned.m16n8k16.row.col.f32.f16.f16.f32 "
        "{%0,%1,%2,%3}, {%4,%5,%6,%7}, {%8,%9}, {%0,%1,%2,%3};"
        : "+f"(c[0]), "+f"(c[1]), "+f"(c[2]), "+f"(c[3])
        : "r"(a[0]), "r"(a[1]), "r"(a[2]), "r"(a[3]), "r"(b[0]), "r"(b[1]));
}

__device__ __forceinline__ void ldsm4(uint32_t* r, uint32_t saddr) {
    asm volatile("ldmatrix.sync.aligned.m8n8.x4.shared.b16 {%0,%1,%2,%3}, [%4];"
                 : "=r"(r[0]), "=r"(r[1]), "=r"(r[2]), "=r"(r[3]) : "r"(saddr));
}

__device__ __forceinline__ void ldsm4t(uint32_t* r, uint32_t saddr) {
    asm volatile("ldmatrix.sync.aligned.m8n8.x4.trans.shared.b16 {%0,%1,%2,%3}, [%4];"
                 : "=r"(r[0]), "=r"(r[1]), "=r"(r[2]), "=r"(r[3]) : "r"(saddr));
}

__device__ __forceinline__ void cp16(void* dst_s, const void* src_g, int sz) {
    uint32_t dst = (uint32_t)__cvta_generic_to_shared(dst_s);
    asm volatile("cp.async.cg.shared.global [%0], [%1], 16, %2;\n"
                 :: "r"(dst), "l"(src_g), "r"(sz));
}

__device__ __forceinline__ uint32_t s2u(const void* p) {
    return (uint32_t)__cvta_generic_to_shared(p);
}

__device__ __forceinline__ uint32_t packh2(float x, float y) {
    __half2 h = __floats2half2_rn(x, y);
    return *(uint32_t*)&h;
}

// ---------------- fused prologue conversions ---------------------------------
// blocks [0, BLK_QKV)                : Q/K/V fp32 -> fp16
// blocks [BLK_QKV, +BLK_W)           : 4 weight matrices fp32 -> fp16
// blocks [BLK_QKV+BLK_W, +BLK_E)     : E transpose -> relT fp16
__global__ void prologue_cvt(
    const float* __restrict__ Q, const float* __restrict__ K,
    const float* __restrict__ V,
    const float* __restrict__ w0, const float* __restrict__ w1,
    const float* __restrict__ w2, const float* __restrict__ w3,
    const float* __restrict__ E,
    __half* __restrict__ qf, __half* __restrict__ kf, __half* __restrict__ vf,
    __half* __restrict__ wh, __half* __restrict__ relT)
{
    int bx = blockIdx.x;
    if (bx < BLK_QKV) {
        int i = bx * 256 + threadIdx.x;
        if (i >= NX4) return;
        float4 a = ((const float4*)Q)[i];
        ((uint2*)qf)[i] = make_uint2(packh2(a.x, a.y), packh2(a.z, a.w));
        float4 b = ((const float4*)K)[i];
        ((uint2*)kf)[i] = make_uint2(packh2(b.x, b.y), packh2(b.z, b.w));
        float4 c = ((const float4*)V)[i];
        ((uint2*)vf)[i] = make_uint2(packh2(c.x, c.y), packh2(c.z, c.w));
    } else if (bx < BLK_QKV + BLK_W) {
        int i = (bx - BLK_QKV) * 256 + threadIdx.x;
        if (i >= NW4) return;
        const float* srcs[4] = {w0, w1, w2, w3};
#pragma unroll
        for (int m = 0; m < 4; m++) {
            float4 a = ((const float4*)srcs[m])[i];
            ((uint2*)(wh + (size_t)m * D_ * D_))[i] =
                make_uint2(packh2(a.x, a.y), packh2(a.z, a.w));
        }
    } else {
        int idx = (bx - BLK_QKV - BLK_W) * 256 + threadIdx.x;
        if (idx >= NE) return;
        int h = idx / (P_ * HD_);
        int rem = idx % (P_ * HD_);
        int p = rem / HD_;
        int d = rem % HD_;
        relT[idx] = __float2half(E[(long long)p * D_ + d * H_ + h]);
    }
}

// ---------------- fp16 tensor-core NT GEMM (3-stage, 1 barrier/ktile) -------
// MODE 0: C fp32 row-major, row stride ldC (scalar stores — ldC may be odd).
// MODE 1: head-split epilogue, C fp16 (paired 4B stores).
// MODE 2: C fp32 row-major, ldC EVEN (paired float2 stores).
template <int MODE>
__global__ __launch_bounds__(256, 2) void gemm_h(
    const __half* __restrict__ A, const __half* __restrict__ Bm,
    void* __restrict__ Cv, int M, int N, int K, int ldC,
    long long sA, long long sB, long long sC, int bmodB)
{
    extern __shared__ uint32_t smh[];   // 3 stages * 2 * 128 * GST
    const int z = blockIdx.z;
    A  += (long long)z * sA;
    Bm += (long long)(z % bmodB) * sB;
    float*  Cf = (float*)Cv  + (long long)z * sC;
    __half* Ch = (__half*)Cv + (long long)z * sC;

    const int bm = blockIdx.y * 128, bn = blockIdx.x * 128;
    const int tid = threadIdx.x;
    const int wid = tid >> 5, lane = tid & 31;
    const int wm = (wid & 3) * 32, wn = (wid >> 2) * 64;
    const int q = lane >> 2, t = lane & 3;

    const uint32_t sbase = s2u(smh);
    const uint32_t STAGEB = 2 * 128 * GST * 4;
    const uint32_t a_byte = (uint32_t)(wm + (lane & 15)) * (GST * 4) + ((lane >> 4) << 4);
    const uint32_t b_byte = (uint32_t)(wn + (lane & 7) + ((lane & 16) ? 8 : 0)) * (GST * 4)
                            + ((lane & 8) ? 16 : 0);

    float acc[2][8][4];
#pragma unroll
    for (int mi = 0; mi < 2; mi++)
#pragma unroll
        for (int ni = 0; ni < 8; ni++)
#pragma unroll
            for (int e = 0; e < 4; e++) acc[mi][ni][e] = 0.f;

    const int ktiles = K >> 6;

#define ISSUE(KT, STAGE)                                                      \
    {                                                                         \
        uint32_t* As = smh + (STAGE) * (2 * 128 * GST);                       \
        uint32_t* Bs = As + 128 * GST;                                        \
        int k0 = (KT) * 64;                                                   \
        _Pragma("unroll")                                                     \
        for (int rep = 0; rep < 4; rep++) {                                   \
            int idx = rep * 256 + tid;                                        \
            int row = idx >> 3, ch = idx & 7;                                 \
            cp16(As + row * GST + ch * 4,                                     \
                 A + (long long)(bm + row) * K + k0 + ch * 8, 16);            \
            int gb = bn + row;                                                \
            int gbc = gb < N ? gb : (N - 1);                                  \
            cp16(Bs + row * GST + ch * 4,                                     \
                 Bm + (long long)gbc * K + k0 + ch * 8, (gb < N) ? 16 : 0);   \
        }                                                                     \
        asm volatile("cp.async.commit_group;\n");                             \
    }

    ISSUE(0, 0);
    if (ktiles > 1) ISSUE(1, 1);

    for (int kt = 0; kt < ktiles; kt++) {
        if (kt + 1 < ktiles) {
            asm volatile("cp.async.wait_group 1;\n");
        } else {
            asm volatile("cp.async.wait_group 0;\n");
        }
        __syncthreads();
        if (kt + 2 < ktiles) ISSUE(kt + 2, (kt + 2) % 3);

        const uint32_t As_s = sbase + (kt % 3) * STAGEB;
        const uint32_t Bs_s = As_s + 128 * GST * 4;
#pragma unroll
        for (int ks = 0; ks < 4; ks++) {
            const uint32_t kbB = ks * 32;
            uint32_t af[2][4];
            ldsm4(af[0], As_s + a_byte + kbB);
            ldsm4(af[1], As_s + a_byte + 16 * GST * 4 + kbB);
            uint32_t bf[8][2];
#pragma unroll
            for (int nj = 0; nj < 4; nj++) {
                uint32_t r[4];
                ldsm4(r, Bs_s + b_byte + nj * 16 * GST * 4 + kbB);
                bf[2 * nj][0] = r[0]; bf[2 * nj][1] = r[1];
                bf[2 * nj + 1][0] = r[2]; bf[2 * nj + 1][1] = r[3];
            }
#pragma unroll
            for (int mi = 0; mi < 2; mi++)
#pragma unroll
                for (int ni = 0; ni < 8; ni++)
                    mma_h(acc[mi][ni], af[mi], bf[ni]);
        }
    }
#undef ISSUE

    // ---- epilogue ----
#pragma unroll
    for (int mi = 0; mi < 2; mi++)
#pragma unroll
        for (int ni = 0; ni < 8; ni++) {
            int gc0 = bn + wn + ni * 8 + t * 2;
#pragma unroll
            for (int half = 0; half < 2; half++) {        // (e0,e1) then (e2,e3)
                int gr = bm + wm + mi * 16 + q + half * 8;
                float v0 = acc[mi][ni][half * 2 + 0];
                float v1 = acc[mi][ni][half * 2 + 1];
                if (MODE == 0) {
                    if (gc0 < N)     Cf[(long long)gr * ldC + gc0]     = v0;
                    if (gc0 + 1 < N) Cf[(long long)gr * ldC + gc0 + 1] = v1;
                } else if (MODE == 2) {
                    *(float2*)(Cf + (long long)gr * ldC + gc0) = make_float2(v0, v1);
                } else {
                    int b = gr >> 11, s = gr & 2047;
                    int h = gc0 >> 6, hd = gc0 & 63;
                    *(uint32_t*)(Ch + (((long long)b * H_ + h) * SQ_ + s) * HD_ + hd) =
                        packh2(v0, v1);
                }
            }
        }
}

// ---------------- banded flash attention (static softmax, R15 exact) --------
__global__ __launch_bounds__(256, 2) void attn_mma(
    const __half* __restrict__ qh, const __half* __restrict__ kh,
    const __half* __restrict__ vh, const float* __restrict__ qrel,
    __half* __restrict__ O)
{
    extern __shared__ uint32_t sma[];
    uint32_t* Qs  = sma;
    uint32_t* Ks0 = Qs + QROWS * AST;
    uint32_t* Vs0 = Ks0 + 2 * ATILE;

    const int i0 = blockIdx.x * QROWS;
    const int h = blockIdx.y, b = blockIdx.z;
    const long long hb = (long long)(b * H_ + h);
    const uint32_t* qb = (const uint32_t*)(qh + hb * SQ_ * HD_);
    const uint32_t* kb = (const uint32_t*)(kh + hb * SK_ * HD_);
    const uint32_t* vb = (const uint32_t*)(vh + hb * SK_ * HD_);
    const float* qr = qrel + hb * SQ_ * P_;

    const int tid = threadIdx.x;
    const int wid = tid >> 5, lane = tid & 31;
    const int q = lane >> 2, t = lane & 3;
    const int wm = wid * 16;
    const int r0 = wm + q, r1 = r0 + 8;

    const uint32_t sbase = s2u(sma);
    const uint32_t Qs_s = sbase;
    const uint32_t Kbase = sbase + QROWS * AST * 4;
    const uint32_t Vbase = Kbase + 2 * ATILE * 4;

    const uint32_t a_byte = (uint32_t)(wm + (lane & 15)) * (AST * 4) + ((lane >> 4) << 4);
    const uint32_t k_byte = (uint32_t)((lane & 7) + ((lane & 16) ? 8 : 0)) * (AST * 4)
                            + ((lane & 8) ? 16 : 0);
    const uint32_t v_byte = (uint32_t)((lane & 7) + ((lane & 8) ? 8 : 0)) * (AST * 4)
                            + ((lane & 16) ? 16 : 0);

#define AISSUE(J0, S)                                                         \
    {                                                                         \
        uint32_t* Kd = Ks0 + (S) * ATILE;                                     \
        uint32_t* Vd = Vs0 + (S) * ATILE;                                     \
        _Pragma("unroll")                                                     \
        for (int l = tid; l < 512; l += 256) {                                \
            int r = l >> 3, ch = l & 7;                                       \
            cp16(Kd + r * AST + ch * 4,                                       \
                 kb + (long long)((J0) + r) * 32 + ch * 4, 16);               \
            cp16(Vd + r * AST + ch * 4,                                       \
                 vb + (long long)((J0) + r) * 32 + ch * 4, 16);               \
        }                                                                     \
        asm volatile("cp.async.commit_group;\n");                             \
    }

    int lo = i0 - RAD_;           if (lo < 0) lo = 0;
    int hi = i0 + QROWS + RAD_;   if (hi > SK_) hi = SK_;

#pragma unroll
    for (int l = tid; l < 1024; l += 256) {
        int r = l >> 3, ch = l & 7;
        cp16(Qs + r * AST + ch * 4, qb + (long long)(i0 + r) * 32 + ch * 4, 16);
    }
    AISSUE(lo, 0);

    float l_part[2] = {0.f, 0.f};      // per-thread partial row sums
    float oacc[8][4];
#pragma unroll
    for (int ni = 0; ni < 8; ni++)
#pragma unroll
        for (int e = 0; e < 4; e++) oacc[ni][e] = 0.f;

    int stage = 0;
    for (int j0 = lo; j0 < hi; j0 += 64) {
        asm volatile("cp.async.wait_group 0;\n");
        __syncthreads();
        if (j0 + 64 < hi) AISSUE(j0 + 64, stage ^ 1);

        const uint32_t Ks_s = Kbase + stage * ATILE * 4;
        const uint32_t Vs_s = Vbase + stage * ATILE * 4;

        // ---- S = Q K^T : 16 rows x 64 keys per warp ----
        float sacc[8][4];
#pragma unroll
        for (int ni = 0; ni < 8; ni++)
#pragma unroll
            for (int e = 0; e < 4; e++) sacc[ni][e] = 0.f;
#pragma unroll
        for (int ks = 0; ks < 4; ks++) {
            const uint32_t kbB = ks * 32;
            uint32_t af[4];
            ldsm4(af, Qs_s + a_byte + kbB);
#pragma unroll
            for (int nj = 0; nj < 4; nj++) {
                uint32_t r[4];
                ldsm4(r, Ks_s + k_byte + nj * 16 * AST * 4 + kbB);
                uint32_t bf0[2] = {r[0], r[1]};
                uint32_t bf1[2] = {r[2], r[3]};
                mma_h(sacc[2 * nj], af, bf0);
                mma_h(sacc[2 * nj + 1], af, bf1);
            }
        }

        // ---- rel gather + mask + scale + exp (no running max) ----
#pragma unroll
        for (int ni = 0; ni < 8; ni++)
#pragma unroll
            for (int e = 0; e < 4; e++) {
                int ri = e >> 1;
                int rl = ri ? r1 : r0;
                int c = ni * 8 + t * 2 + (e & 1);
                int delta = (j0 + c) - (i0 + rl);
                float p = 0.f;
                if (delta >= -RAD_ && delta <= RAD_) {
                    int pid = min(max(delta, -R_), R_) + R_;
                    float s = (sacc[ni][e] +
                               __ldg(qr + (long long)(i0 + rl) * P_ + pid)) * 0.125f;
                    p = __expf(s);
                }
                sacc[ni][e] = p;
                l_part[ri] += p;
            }

        // ---- O += P V : QK C-frags pass directly into PV A-frags ----
#pragma unroll
        for (int ks = 0; ks < 4; ks++) {
            uint32_t af[4];
            af[0] = packh2(sacc[2 * ks][0], sacc[2 * ks][1]);
            af[1] = packh2(sacc[2 * ks][2], sacc[2 * ks][3]);
            af[2] = packh2(sacc[2 * ks + 1][0], sacc[2 * ks + 1][1]);
            af[3] = packh2(sacc[2 * ks + 1][2], sacc[2 * ks + 1][3]);
#pragma unroll
            for (int nj = 0; nj < 4; nj++) {
                uint32_t r[4];
                ldsm4t(r, Vs_s + v_byte + ks * 16 * AST * 4 + nj * 32);
                uint32_t bf0[2] = {r[0], r[1]};
                uint32_t bf1[2] = {r[2], r[3]};
                mma_h(oacc[2 * nj], af, bf0);
                mma_h(oacc[2 * nj + 1], af, bf1);
            }
        }
        stage ^= 1;
    }
#undef AISSUE

    // ---- one final row-sum reduction (quad shfl) + normalize + store ----
    float inv[2];
#pragma unroll
    for (int i = 0; i < 2; i++) {
        float s = l_part[i];
        s += __shfl_xor_sync(0xffffffffu, s, 1);
        s += __shfl_xor_sync(0xffffffffu, s, 2);
        inv[i] = 1.0f / s;
    }
#pragma unroll
    for (int ni = 0; ni < 8; ni++)
#pragma unroll
        for (int e = 0; e < 4; e++) {
            int ri = e >> 1;
            int rl = ri ? r1 : r0;
            int c = ni * 8 + t * 2 + (e & 1);
            O[((long long)b * SQ_ + i0 + rl) * D_ + c * H_ + h] =
                __float2half(oacc[ni][e] * inv[ri]);
        }
}

// ---------------- launch -----------------------------------------------------
extern "C" void kernel_launch(void* const* d_in, const int* in_sizes, int n_in,
                              void* d_out, int out_size)
{
    const float* Q  = (const float*)d_in[0];
    const float* K  = (const float*)d_in[1];
    const float* V  = (const float*)d_in[2];
    const float* Wq = (const float*)d_in[3];
    const float* Wk = (const float*)d_in[4];
    const float* Wv = (const float*)d_in[5];
    const float* Wo = (const float*)d_in[6];
    const float* E  = (const float*)d_in[7];
    float* out = (float*)d_out;

    __half *xf, *wh, *heads, *relT, *o;
    float *qrel;
    cudaGetSymbolAddress((void**)&xf,    g_xf);
    cudaGetSymbolAddress((void**)&wh,    g_wh);
    cudaGetSymbolAddress((void**)&heads, g_heads);
    cudaGetSymbolAddress((void**)&relT,  g_relT);
    cudaGetSymbolAddress((void**)&qrel,  g_qrel);
    cudaGetSymbolAddress((void**)&o,     g_o);

    __half* qf = xf + 0 * (size_t)B_ * SQ_ * D_;
    __half* kf = xf + 1 * (size_t)B_ * SQ_ * D_;
    __half* vf = xf + 2 * (size_t)B_ * SQ_ * D_;
    __half* qh = heads;
    __half* kh = heads + HS;
    __half* vh = heads + 2 * HS;

    const int gemm_smem = 3 * 2 * 128 * GST * (int)sizeof(uint32_t);   // 110592
    cudaFuncSetAttribute((const void*)gemm_h<0>, cudaFuncAttributeMaxDynamicSharedMemorySize, gemm_smem);
    cudaFuncSetAttribute((const void*)gemm_h<1>, cudaFuncAttributeMaxDynamicSharedMemorySize, gemm_smem);
    cudaFuncSetAttribute((const void*)gemm_h<2>, cudaFuncAttributeMaxDynamicSharedMemorySize, gemm_smem);

    dim3 blk(256);

    // fused prologue: QKV cvt + weight cvt + E transpose in one launch
    int nProl = BLK_QKV + BLK_W + BLK_E;
    prologue_cvt<<<nProl, 256>>>(Q, K, V, Wq, Wk, Wv, Wo, E,
                                 qf, kf, vf, wh, relT);

    // fused Q/K/V projections (z selects input/weight/output)
    dim3 gproj(1024 / 128, 4096 / 128, 3);
    gemm_h<1><<<gproj, blk, gemm_smem>>>(qf, wh, heads, 4096, 1024, 1024, 0,
                                         (long long)B_ * SQ_ * D_, (long long)D_ * D_,
                                         (long long)HS, 3);

    // Q_rel (N=257, odd ldC -> scalar store path)
    dim3 gqr((P_ + 127) / 128, SQ_ / 128, B_ * H_);
    gemm_h<0><<<gqr, blk, gemm_smem>>>(qh, relT, qrel, SQ_, P_, HD_, P_,
                                       (long long)SQ_ * HD_, (long long)P_ * HD_,
                                       (long long)SQ_ * P_, H_);

    // banded attention (static softmax)
    int asmem = (QROWS * AST + 4 * ATILE) * (int)sizeof(uint32_t);   // 55296
    cudaFuncSetAttribute(attn_mma, cudaFuncAttributeMaxDynamicSharedMemorySize, asmem);
    dim3 gattn(SQ_ / QROWS, H_, B_);
    attn_mma<<<gattn, blk, asmem>>>(qh, kh, vh, qrel, o);

    // output projection -> fp32 out (even ldC -> paired float2 stores)
    dim3 gout(1024 / 128, 4096 / 128, 1);
    gemm_h<2><<<gout, blk, gemm_smem>>>(o, wh + 3 * (size_t)D_ * D_, out,
                                        4096, 1024, 1024, 1024, 0, 0, 0, 1);

    (void)in_sizes; (void)n_in; (void)out_size;
}